// round 1
// baseline (speedup 1.0000x reference)
#include <cuda_runtime.h>

// out = softmax(normalize(Q) @ normalize(K)^T) @ K
// N=65536, K=4096, D=128, fp32. Scores in [-1,1] => no max-subtraction needed.
// Key insight: normalized keys = raw_keys * inv_norm, and V = raw_keys, so we
// keep ONE raw key tile in smem and fold inv_norm into the score epilogue.

#define BM 64
#define BK 64
#define DIM 128
#define NTHREADS 256
#define QS_STRIDE 132   // 128 + 4 pad (floats) to break bank conflicts
#define KS_STRIDE 132
#define PS_STRIDE 68    // 64 + 4 pad

typedef unsigned long long ull;

// Packed dual-fp32 FMA (sm_103a FFMA2) — only reachable via PTX fma.rn.f32x2.
__device__ __forceinline__ void fma2(ull& d, ull a, ull b) {
    asm("fma.rn.f32x2 %0, %1, %2, %0;" : "+l"(d) : "l"(a), "l"(b));
}
__device__ __forceinline__ ull dup2(float x) {
    ull r; asm("mov.b64 %0, {%1, %1};" : "=l"(r) : "f"(x)); return r;
}
__device__ __forceinline__ float2 unpack2(ull v) {
    float2 f; asm("mov.b64 {%0, %1}, %2;" : "=f"(f.x), "=f"(f.y) : "l"(v)); return f;
}

__global__ __launch_bounds__(NTHREADS, 2)
void mb_retrieve_kernel(const float* __restrict__ queries,
                        const float* __restrict__ keys,
                        float* __restrict__ out, int K) {
    extern __shared__ float sm[];
    float* Qs   = sm;                       // BM x QS_STRIDE (normalized Q)
    float* Ks   = Qs + BM * QS_STRIDE;      // BK x KS_STRIDE (RAW keys tile)
    float* Ps   = Ks + BK * KS_STRIDE;      // BM x PS_STRIDE (exp scores)
    float* kinv = Ps + BM * PS_STRIDE;      // BK per-row 1/max(||k||,eps)

    const int tid  = threadIdx.x;
    const int tx   = tid & 15;   // 16 col groups
    const int ty   = tid >> 4;   // 16 row groups
    const int warp = tid >> 5;
    const int lane = tid & 31;

    const int qrow0 = blockIdx.x * BM;

    // ---- Load + L2-normalize Q tile: one row per warp-iteration (32 float4 = 128 f) ----
    const float4* q4 = (const float4*)queries;
    #pragma unroll
    for (int it = 0; it < BM / 8; ++it) {
        int row = warp + it * 8;
        float4 v = q4[(size_t)(qrow0 + row) * (DIM / 4) + lane];
        float ss = v.x * v.x + v.y * v.y + v.z * v.z + v.w * v.w;
        #pragma unroll
        for (int o = 16; o > 0; o >>= 1) ss += __shfl_xor_sync(0xffffffffu, ss, o);
        float sc = 1.0f / fmaxf(sqrtf(ss), 1e-12f);
        v.x *= sc; v.y *= sc; v.z *= sc; v.w *= sc;
        *(float4*)&Qs[row * QS_STRIDE + lane * 4] = v;
    }

    // O accumulators: 4 rows x 8 cols as 4 f32x2 pairs; Z partials per row.
    ull Op[4][4];
    float zacc[4];
    #pragma unroll
    for (int r = 0; r < 4; ++r) {
        zacc[r] = 0.f;
        #pragma unroll
        for (int c = 0; c < 4; ++c) Op[r][c] = 0ull;
    }

    const float4* k4 = (const float4*)keys;
    const int ntiles = K / BK;
    for (int t = 0; t < ntiles; ++t) {
        __syncthreads();  // previous PV done with Ks / Ps

        // ---- Load RAW key tile, compute inv-norms on the fly (row per warp-iter) ----
        #pragma unroll
        for (int it = 0; it < BK / 8; ++it) {
            int row = warp + it * 8;
            float4 v = k4[(size_t)(t * BK + row) * (DIM / 4) + lane];
            float ss = v.x * v.x + v.y * v.y + v.z * v.z + v.w * v.w;
            #pragma unroll
            for (int o = 16; o > 0; o >>= 1) ss += __shfl_xor_sync(0xffffffffu, ss, o);
            *(float4*)&Ks[row * KS_STRIDE + lane * 4] = v;
            if (lane == 0) kinv[row] = 1.0f / fmaxf(sqrtf(ss), 1e-12f);
        }
        __syncthreads();

        // ---- S = Qn(4 rows) . Kraw(4 cols), d-pair packed f32x2 accumulation ----
        ull sa[4][4];
        #pragma unroll
        for (int r = 0; r < 4; ++r)
            #pragma unroll
            for (int c = 0; c < 4; ++c) sa[r][c] = 0ull;

        #pragma unroll 4
        for (int d = 0; d < DIM; d += 4) {
            ulonglong2 qu[4], ku[4];
            #pragma unroll
            for (int r = 0; r < 4; ++r)
                qu[r] = *(const ulonglong2*)&Qs[(ty * 4 + r) * QS_STRIDE + d];
            #pragma unroll
            for (int c = 0; c < 4; ++c)
                ku[c] = *(const ulonglong2*)&Ks[(tx * 4 + c) * KS_STRIDE + d];
            #pragma unroll
            for (int r = 0; r < 4; ++r)
                #pragma unroll
                for (int c = 0; c < 4; ++c) {
                    fma2(sa[r][c], qu[r].x, ku[c].x);
                    fma2(sa[r][c], qu[r].y, ku[c].y);
                }
        }

        // ---- epilogue: fold key inv-norm, exp (scores bounded: no max needed) ----
        #pragma unroll
        for (int r = 0; r < 4; ++r)
            #pragma unroll
            for (int c = 0; c < 4; ++c) {
                float2 f = unpack2(sa[r][c]);
                float s = (f.x + f.y) * kinv[tx * 4 + c];
                float p = __expf(s);
                zacc[r] += p;
                Ps[(ty * 4 + r) * PS_STRIDE + tx * 4 + c] = p;
            }
        __syncthreads();

        // ---- O += P(4 rows) x Kraw(8 cols), col-pair packed f32x2 ----
        #pragma unroll 2
        for (int kk = 0; kk < BK; kk += 4) {
            float4 pr[4];
            #pragma unroll
            for (int r = 0; r < 4; ++r)
                pr[r] = *(const float4*)&Ps[(ty * 4 + r) * PS_STRIDE + kk];
            #pragma unroll
            for (int j = 0; j < 4; ++j) {
                ulonglong2 v0 = *(const ulonglong2*)&Ks[(kk + j) * KS_STRIDE + tx * 8];
                ulonglong2 v1 = *(const ulonglong2*)&Ks[(kk + j) * KS_STRIDE + tx * 8 + 4];
                #pragma unroll
                for (int r = 0; r < 4; ++r) {
                    float pj = (j == 0) ? pr[r].x : (j == 1) ? pr[r].y
                             : (j == 2) ? pr[r].z : pr[r].w;
                    ull pd = dup2(pj);
                    fma2(Op[r][0], pd, v0.x);
                    fma2(Op[r][1], pd, v0.y);
                    fma2(Op[r][2], pd, v1.x);
                    fma2(Op[r][3], pd, v1.y);
                }
            }
        }
    }

    // ---- Z reduction across the 16 tx threads sharing each row (reuse Ps) ----
    __syncthreads();
    #pragma unroll
    for (int r = 0; r < 4; ++r) Ps[(ty * 4 + r) * 16 + tx] = zacc[r];
    __syncthreads();

    #pragma unroll
    for (int r = 0; r < 4; ++r) {
        float Z = 0.f;
        #pragma unroll
        for (int i = 0; i < 16; ++i) Z += Ps[(ty * 4 + r) * 16 + i];
        float invZ = 1.0f / Z;
        int grow = qrow0 + ty * 4 + r;
        float2 a  = unpack2(Op[r][0]);
        float2 b  = unpack2(Op[r][1]);
        float2 c2 = unpack2(Op[r][2]);
        float2 d2 = unpack2(Op[r][3]);
        float4 o0 = make_float4(a.x * invZ, a.y * invZ, b.x * invZ, b.y * invZ);
        float4 o1 = make_float4(c2.x * invZ, c2.y * invZ, d2.x * invZ, d2.y * invZ);
        *(float4*)&out[(size_t)grow * DIM + tx * 8]     = o0;
        *(float4*)&out[(size_t)grow * DIM + tx * 8 + 4] = o1;
    }
}

extern "C" void kernel_launch(void* const* d_in, const int* in_sizes, int n_in,
                              void* d_out, int out_size) {
    const float* queries = (const float*)d_in[0];
    const float* keys    = (const float*)d_in[1];
    float* out = (float*)d_out;
    int N = in_sizes[0] / DIM;   // 65536
    int K = in_sizes[1] / DIM;   // 4096

    int smem = (BM * QS_STRIDE + BK * KS_STRIDE + BM * PS_STRIDE + BK) * (int)sizeof(float);
    cudaFuncSetAttribute(mb_retrieve_kernel,
                         cudaFuncAttributeMaxDynamicSharedMemorySize, smem);
    mb_retrieve_kernel<<<N / BM, NTHREADS, smem>>>(queries, keys, out, K);
}

// round 4
// speedup vs baseline: 13.6027x; 13.6027x over previous
#include <cuda_runtime.h>
#include <cuda_bf16.h>
#include <cstdint>

// out = softmax(normalize(Q)@normalize(K)^T) @ K,  N=65536, K=4096, D=128, fp32
// Path: legacy tensor-core mma.sync (bf16, fp32 accum) — tcgen05.ld is not
// available at this toolchain's PTX target (sm_103 base).
// Numerics: out = (colsum(V) + (P-1)@V)/Z, P-1 in bf16, V in bf16 (hi only;
// low-order V correction averages out below 1e-4 — see analysis).

#define NQ 65536
#define NKEY 4096
#define DIM 128
#define BM 128
#define BK 128
#define NTILES (NKEY / BK)
#define NTHREADS 256
#define SROW 272          // smem row stride in bytes (128 bf16 + 16B pad)

__device__ __nv_bfloat16 g_Qbf[(size_t)NQ * DIM];    // normalized Q, bf16
__device__ __nv_bfloat16 g_Kn [(size_t)NKEY * DIM];  // normalized K, bf16
__device__ __nv_bfloat16 g_Vt [(size_t)DIM * NKEY];  // raw keys^T (d-major), bf16
__device__ float g_colsum[DIM];                      // exact fp32 column sums of V

// ---------------- helpers ----------------
__device__ __forceinline__ uint32_t smem_u32(const void* p) {
    uint32_t a;
    asm("{ .reg .u64 t; cvta.to.shared.u64 t, %1; cvt.u32.u64 %0, t; }" : "=r"(a) : "l"(p));
    return a;
}
__device__ __forceinline__ void ldsm4(uint32_t& r0, uint32_t& r1, uint32_t& r2, uint32_t& r3,
                                      uint32_t addr) {
    asm volatile("ldmatrix.sync.aligned.m8n8.x4.shared.b16 {%0,%1,%2,%3}, [%4];"
                 : "=r"(r0), "=r"(r1), "=r"(r2), "=r"(r3) : "r"(addr));
}
__device__ __forceinline__ void mma16816(float* d, const uint32_t* a, uint32_t b0, uint32_t b1) {
    asm volatile("mma.sync.aligned.m16n8k16.row.col.f32.bf16.bf16.f32 "
                 "{%0,%1,%2,%3}, {%4,%5,%6,%7}, {%8,%9}, {%0,%1,%2,%3};"
                 : "+f"(d[0]), "+f"(d[1]), "+f"(d[2]), "+f"(d[3])
                 : "r"(a[0]), "r"(a[1]), "r"(a[2]), "r"(a[3]), "r"(b0), "r"(b1));
}
__device__ __forceinline__ uint32_t packbf(float hi, float lo) {
    uint32_t r; asm("cvt.rn.bf16x2.f32 %0, %1, %2;" : "=r"(r) : "f"(hi), "f"(lo)); return r;
}
__device__ __forceinline__ void cp16(uint32_t saddr, const void* g) {
    asm volatile("cp.async.cg.shared.global [%0], [%1], 16;" :: "r"(saddr), "l"(g));
}
#define CP_COMMIT() asm volatile("cp.async.commit_group;" ::: "memory")
#define CP_WAIT1()  asm volatile("cp.async.wait_group 1;" ::: "memory")

// ---------------- prep kernels ----------------
__global__ void prep_q(const float* __restrict__ q) {
    int row = blockIdx.x * 8 + (threadIdx.x >> 5);
    int lane = threadIdx.x & 31;
    float4 v = ((const float4*)q)[(size_t)row * 32 + lane];
    float ss = v.x * v.x + v.y * v.y + v.z * v.z + v.w * v.w;
    #pragma unroll
    for (int o = 16; o > 0; o >>= 1) ss += __shfl_xor_sync(0xffffffffu, ss, o);
    float sc = 1.0f / fmaxf(sqrtf(ss), 1e-12f);
    __nv_bfloat162* dst = (__nv_bfloat162*)(g_Qbf + (size_t)row * DIM + lane * 4);
    dst[0] = __float22bfloat162_rn(make_float2(v.x * sc, v.y * sc));
    dst[1] = __float22bfloat162_rn(make_float2(v.z * sc, v.w * sc));
}

__global__ void prep_k(const float* __restrict__ keys) {
    int row = blockIdx.x * 8 + (threadIdx.x >> 5);
    int lane = threadIdx.x & 31;
    float4 v = ((const float4*)keys)[(size_t)row * 32 + lane];
    float ss = v.x * v.x + v.y * v.y + v.z * v.z + v.w * v.w;
    #pragma unroll
    for (int o = 16; o > 0; o >>= 1) ss += __shfl_xor_sync(0xffffffffu, ss, o);
    float sc = 1.0f / fmaxf(sqrtf(ss), 1e-12f);
    __nv_bfloat162* dst = (__nv_bfloat162*)(g_Kn + (size_t)row * DIM + lane * 4);
    dst[0] = __float22bfloat162_rn(make_float2(v.x * sc, v.y * sc));
    dst[1] = __float22bfloat162_rn(make_float2(v.z * sc, v.w * sc));
    float xs[4] = {v.x, v.y, v.z, v.w};
    #pragma unroll
    for (int j = 0; j < 4; ++j)
        g_Vt[(size_t)(lane * 4 + j) * NKEY + row] = __float2bfloat16(xs[j]);
}

__global__ void prep_colsum(const float* __restrict__ keys) {
    __shared__ float red[256];
    int d = blockIdx.x;
    float s = 0.f;
    for (int k = threadIdx.x; k < NKEY; k += 256) s += keys[(size_t)k * DIM + d];
    red[threadIdx.x] = s;
    __syncthreads();
    for (int o = 128; o > 0; o >>= 1) {
        if ((int)threadIdx.x < o) red[threadIdx.x] += red[threadIdx.x + o];
        __syncthreads();
    }
    if (threadIdx.x == 0) g_colsum[d] = red[0];
}

// ---------------- main kernel ----------------
// smem: double-buffered K (keys x d) + V^T (d x keys) tiles, 272B rows + colsum
enum { B0K = 0, B0V = 34816, B1K = 69632, B1V = 104448, CSOF = 139264, SMTOT = 139776 };

__device__ __forceinline__ void issue_tile(uint32_t sb, int buf, int t, int tid) {
    uint32_t kb = sb + (buf ? B1K : B0K);
    uint32_t vb = sb + (buf ? B1V : B0V);
    const __nv_bfloat16* ks = g_Kn + (size_t)t * BK * DIM;
    const __nv_bfloat16* vs = g_Vt + (size_t)t * BK;
    #pragma unroll
    for (int c = 0; c < 8; ++c) {
        int chunk = c * 256 + tid;        // 2048 16B chunks per tile
        int r = chunk >> 4, o = chunk & 15;
        cp16(kb + r * SROW + o * 16, ks + (size_t)r * DIM + o * 8);
    }
    #pragma unroll
    for (int c = 0; c < 8; ++c) {
        int chunk = c * 256 + tid;
        int r = chunk >> 4, o = chunk & 15;
        cp16(vb + r * SROW + o * 16, vs + (size_t)r * NKEY + o * 8);
    }
}

__global__ __launch_bounds__(NTHREADS, 1)
void mb_main(float* __restrict__ out) {
    extern __shared__ char sm[];
    const uint32_t sb = smem_u32(sm);
    const int tid = threadIdx.x, wid = tid >> 5, lane = tid & 31;

    if (tid < DIM) ((float*)(sm + CSOF))[tid] = g_colsum[tid];

    // Stage this CTA's Q tile into buf1-K region, build register A-fragments.
    {
        const __nv_bfloat16* qs = g_Qbf + (size_t)blockIdx.x * BM * DIM;
        #pragma unroll
        for (int c = 0; c < 8; ++c) {
            int chunk = c * 256 + tid;
            int r = chunk >> 4, o = chunk & 15;
            *(uint4*)(sm + B1K + r * SROW + o * 16) = *(const uint4*)(qs + (size_t)r * DIM + o * 8);
        }
    }
    __syncthreads();
    uint32_t qa[8][4];
    {
        int row = wid * 16 + (lane & 15);
        int colh = (lane >> 4) * 8;
        #pragma unroll
        for (int k = 0; k < 8; ++k)
            ldsm4(qa[k][0], qa[k][1], qa[k][2], qa[k][3],
                  sb + B1K + row * SROW + (k * 16 + colh) * 2);
    }
    __syncthreads();   // all warps done reading Q before buf1 is reused

    float o_acc[16][4];
    #pragma unroll
    for (int j = 0; j < 16; ++j)
        #pragma unroll
        for (int c = 0; c < 4; ++c) o_acc[j][c] = 0.f;
    float zlo = 0.f, zhi = 0.f;

    const int bg  = (lane >> 3) & 1;   // block row-half selector
    const int bc  = (lane >> 4);       // block col-half selector
    const int br  = lane & 7;

    issue_tile(sb, 0, 0, tid);
    CP_COMMIT();

    for (int t = 0; t < NTILES; ++t) {
        int buf = t & 1;
        if (t + 1 < NTILES) issue_tile(sb, buf ^ 1, t + 1, tid);
        CP_COMMIT();
        CP_WAIT1();
        __syncthreads();

        uint32_t kb = sb + (buf ? B1K : B0K);
        uint32_t vb = sb + (buf ? B1V : B0V);

        #pragma unroll
        for (int s = 0; s < 8; ++s) {
            // ---- S: two n8-tiles (16 keys) vs this warp's 16 query rows ----
            float a0[4] = {0.f, 0.f, 0.f, 0.f}, a1[4] = {0.f, 0.f, 0.f, 0.f};
            #pragma unroll
            for (int k = 0; k < 8; ++k) {
                uint32_t r0, r1, r2, r3;
                ldsm4(r0, r1, r2, r3,
                      kb + (uint32_t)((s * 16 + bg * 8 + br) * SROW + (k * 16 + bc * 8) * 2));
                mma16816(a0, qa[k], r0, r2);
                mma16816(a1, qa[k], r1, r3);
            }
            // ---- exp(s)-1, Z partials, repack as PV A-fragment (regs only) ----
            float p00 = __expf(a0[0]) - 1.f, p01 = __expf(a0[1]) - 1.f;
            float p02 = __expf(a0[2]) - 1.f, p03 = __expf(a0[3]) - 1.f;
            float p10 = __expf(a1[0]) - 1.f, p11 = __expf(a1[1]) - 1.f;
            float p12 = __expf(a1[2]) - 1.f, p13 = __expf(a1[3]) - 1.f;
            zlo += (p00 + p01) + (p10 + p11);
            zhi += (p02 + p03) + (p12 + p13);
            uint32_t pa[4];
            pa[0] = packbf(p01, p00);
            pa[1] = packbf(p03, p02);
            pa[2] = packbf(p11, p10);
            pa[3] = packbf(p13, p12);
            // ---- O += P(16 keys) @ V(16 keys x 128 d) ----
            #pragma unroll
            for (int j = 0; j < 8; ++j) {
                uint32_t r0, r1, r2, r3;
                ldsm4(r0, r1, r2, r3,
                      vb + (uint32_t)((j * 16 + bg * 8 + br) * SROW + (s * 16 + bc * 8) * 2));
                mma16816(o_acc[2 * j],     pa, r0, r2);
                mma16816(o_acc[2 * j + 1], pa, r1, r3);
            }
        }
    }

    // ---- epilogue: Z warp-reduce, add colsum, normalize, write ----
    zlo += __shfl_xor_sync(0xffffffffu, zlo, 1);
    zlo += __shfl_xor_sync(0xffffffffu, zlo, 2);
    zhi += __shfl_xor_sync(0xffffffffu, zhi, 1);
    zhi += __shfl_xor_sync(0xffffffffu, zhi, 2);
    float invZlo = 1.0f / ((float)NKEY + zlo);
    float invZhi = 1.0f / ((float)NKEY + zhi);

    const float* cs = (const float*)(sm + CSOF);
    size_t row0 = (size_t)blockIdx.x * BM + wid * 16 + (lane >> 2);
    int col0 = (lane & 3) * 2;
    #pragma unroll
    for (int j = 0; j < 16; ++j) {
        int c = j * 8 + col0;
        float2 v0 = make_float2((cs[c] + o_acc[j][0]) * invZlo,
                                (cs[c + 1] + o_acc[j][1]) * invZlo);
        float2 v1 = make_float2((cs[c] + o_acc[j][2]) * invZhi,
                                (cs[c + 1] + o_acc[j][3]) * invZhi);
        *(float2*)&out[row0 * DIM + c] = v0;
        *(float2*)&out[(row0 + 8) * DIM + c] = v1;
    }
}

// ---------------- launch ----------------
extern "C" void kernel_launch(void* const* d_in, const int* in_sizes, int n_in,
                              void* d_out, int out_size) {
    const float* queries = (const float*)d_in[0];
    const float* keys    = (const float*)d_in[1];
    float* out = (float*)d_out;
    int N = in_sizes[0] / DIM;
    int K = in_sizes[1] / DIM;

    prep_q<<<N / 8, 256>>>(queries);
    prep_k<<<K / 8, 256>>>(keys);
    prep_colsum<<<DIM, 256>>>(keys);

    cudaFuncSetAttribute(mb_main, cudaFuncAttributeMaxDynamicSharedMemorySize, SMTOT);
    mb_main<<<N / BM, NTHREADS, SMTOT>>>(out);
}

// round 8
// speedup vs baseline: 13.8167x; 1.0157x over previous
#include <cuda_runtime.h>
#include <cuda_fp16.h>
#include <cstdint>

// out = softmax(normalize(Q)@normalize(K)^T) @ K,  N=65536, K=4096, D=128, fp32
// R3-proven dataflow, fp16, 2 CTAs/SM.
//   S  = Qn(fp16) @ Kn(fp16)^T          (non-trans ldsm4 on [key][d] tile)
//   O += (exp(S)-1)(fp16) @ V            (non-trans ldsm4 on V^T [d][key] tile)
//   out = (colsum(V) + O) / Z,  V = raw keys fp16
// R7 fix: Q staging copied only 8/16 chunks per 256B row (dims 64..127 were
// garbage smem -> NaN). Now 1024 chunks, r=chunk>>4, o=chunk&15.

#define NQ 65536
#define NKEY 4096
#define DIM 128
#define BM 64
#define BK 64
#define NTILES (NKEY / BK)
#define NTHREADS 128
#define SROWK 272         // K tile row stride bytes (128 fp16 + 16B pad)
#define SROWV 144         // V^T tile row stride bytes (64 fp16 + 16B pad)

__device__ __align__(16) __half g_Qh[(size_t)NQ * DIM];    // normalized Q, fp16
__device__ __align__(16) __half g_Kh[(size_t)NKEY * DIM];  // NORMALIZED keys, fp16
__device__ __align__(16) __half g_Vt[(size_t)DIM * NKEY];  // raw keys^T [d][key], fp16
__device__ __align__(16) float  g_colsum[DIM];             // fp32 colsums of raw keys

// ---------------- helpers ----------------
__device__ __forceinline__ uint32_t smem_u32(const void* p) {
    uint32_t a;
    asm("{ .reg .u64 t; cvta.to.shared.u64 t, %1; cvt.u32.u64 %0, t; }" : "=r"(a) : "l"(p));
    return a;
}
__device__ __forceinline__ void ldsm4(uint32_t& r0, uint32_t& r1, uint32_t& r2, uint32_t& r3,
                                      uint32_t addr) {
    asm volatile("ldmatrix.sync.aligned.m8n8.x4.shared.b16 {%0,%1,%2,%3}, [%4];"
                 : "=r"(r0), "=r"(r1), "=r"(r2), "=r"(r3) : "r"(addr));
}
__device__ __forceinline__ void mma16816(float* d, const uint32_t* a, uint32_t b0, uint32_t b1) {
    asm volatile("mma.sync.aligned.m16n8k16.row.col.f32.f16.f16.f32 "
                 "{%0,%1,%2,%3}, {%4,%5,%6,%7}, {%8,%9}, {%0,%1,%2,%3};"
                 : "+f"(d[0]), "+f"(d[1]), "+f"(d[2]), "+f"(d[3])
                 : "r"(a[0]), "r"(a[1]), "r"(a[2]), "r"(a[3]), "r"(b0), "r"(b1));
}
__device__ __forceinline__ uint32_t packh(float hi, float lo) {
    uint32_t r; asm("cvt.rn.f16x2.f32 %0, %1, %2;" : "=r"(r) : "f"(hi), "f"(lo)); return r;
}
__device__ __forceinline__ void cp16(uint32_t saddr, const void* g) {
    asm volatile("cp.async.cg.shared.global [%0], [%1], 16;" :: "r"(saddr), "l"(g));
}
#define CP_COMMIT() asm volatile("cp.async.commit_group;" ::: "memory")
#define CP_WAIT1()  asm volatile("cp.async.wait_group 1;" ::: "memory")

// ---------------- prep kernels ----------------
__global__ void prep_q(const float* __restrict__ q) {
    int row = blockIdx.x * 8 + (threadIdx.x >> 5);
    int lane = threadIdx.x & 31;
    float4 v = ((const float4*)q)[(size_t)row * 32 + lane];
    float ss = v.x * v.x + v.y * v.y + v.z * v.z + v.w * v.w;
    #pragma unroll
    for (int o = 16; o > 0; o >>= 1) ss += __shfl_xor_sync(0xffffffffu, ss, o);
    float sc = 1.0f / fmaxf(sqrtf(ss), 1e-12f);
    __half2* dst = (__half2*)(g_Qh + (size_t)row * DIM + lane * 4);
    dst[0] = __float22half2_rn(make_float2(v.x * sc, v.y * sc));
    dst[1] = __float22half2_rn(make_float2(v.z * sc, v.w * sc));
}

__global__ void prep_k(const float* __restrict__ keys) {
    int row = blockIdx.x * 8 + (threadIdx.x >> 5);
    int lane = threadIdx.x & 31;
    float4 v = ((const float4*)keys)[(size_t)row * 32 + lane];
    float ss = v.x * v.x + v.y * v.y + v.z * v.z + v.w * v.w;
    #pragma unroll
    for (int o = 16; o > 0; o >>= 1) ss += __shfl_xor_sync(0xffffffffu, ss, o);
    float sc = 1.0f / fmaxf(sqrtf(ss), 1e-12f);
    __half2* dst = (__half2*)(g_Kh + (size_t)row * DIM + lane * 4);
    dst[0] = __float22half2_rn(make_float2(v.x * sc, v.y * sc));
    dst[1] = __float22half2_rn(make_float2(v.z * sc, v.w * sc));
    float xs[4] = {v.x, v.y, v.z, v.w};
    #pragma unroll
    for (int j = 0; j < 4; ++j)
        g_Vt[(size_t)(lane * 4 + j) * NKEY + row] = __float2half(xs[j]);
}

__global__ void prep_colsum(const float* __restrict__ keys) {
    __shared__ float red[256];
    int d = blockIdx.x;
    float s = 0.f;
    for (int k = threadIdx.x; k < NKEY; k += 256) s += keys[(size_t)k * DIM + d];
    red[threadIdx.x] = s;
    __syncthreads();
    for (int o = 128; o > 0; o >>= 1) {
        if ((int)threadIdx.x < o) red[threadIdx.x] += red[threadIdx.x + o];
        __syncthreads();
    }
    if (threadIdx.x == 0) g_colsum[d] = red[0];
}

// ---------------- main kernel ----------------
// smem: double-buffered { K tile 64x272B + V^T tile 128x144B } + colsum
enum { B0K = 0, B0V = 17408, B1K = 35840, B1V = 53248, CSOF = 71680, SMTOT = 72192 };

__device__ __forceinline__ void issue_tile(uint32_t sb, int buf, int t, int tid) {
    uint32_t kb = sb + (buf ? B1K : B0K);
    uint32_t vb = sb + (buf ? B1V : B0V);
    const __half* ks = g_Kh + (size_t)t * BK * DIM;
    const __half* vs = g_Vt + (size_t)t * BK;
    #pragma unroll
    for (int c = 0; c < 8; ++c) {
        int chunk = c * NTHREADS + tid;      // 1024 chunks = 64 rows x 16
        int r = chunk >> 4, o = chunk & 15;
        cp16(kb + r * SROWK + o * 16, ks + (size_t)r * DIM + o * 8);
    }
    #pragma unroll
    for (int c = 0; c < 8; ++c) {
        int chunk = c * NTHREADS + tid;      // 1024 chunks = 128 rows x 8
        int r = chunk >> 3, o = chunk & 7;
        cp16(vb + r * SROWV + o * 16, vs + (size_t)r * NKEY + o * 8);
    }
}

__global__ __launch_bounds__(NTHREADS, 2)
void mb_main(float* __restrict__ out) {
    extern __shared__ char sm[];
    const uint32_t sb = smem_u32(sm);
    const int tid = threadIdx.x, wid = tid >> 5, lane = tid & 31;

    if (tid < DIM) ((float*)(sm + CSOF))[tid] = g_colsum[tid];

    // Stage this CTA's 64-row Q tile into B1K region (FULL 256B rows!).
    {
        const __half* qs = g_Qh + (size_t)blockIdx.x * BM * DIM;
        #pragma unroll
        for (int c = 0; c < 8; ++c) {
            int chunk = c * NTHREADS + tid;  // 1024 chunks = 64 rows x 16
            int r = chunk >> 4, o = chunk & 15;
            *(uint4*)(sm + B1K + r * SROWK + o * 16) =
                *(const uint4*)(qs + (size_t)r * DIM + o * 8);
        }
    }
    __syncthreads();
    uint32_t qa[8][4];
    {
        int row = wid * 16 + (lane & 15);
        int colh = (lane >> 4) * 8;
        #pragma unroll
        for (int k = 0; k < 8; ++k)
            ldsm4(qa[k][0], qa[k][1], qa[k][2], qa[k][3],
                  sb + B1K + row * SROWK + (k * 16 + colh) * 2);
    }

    float o_acc[16][4];
    #pragma unroll
    for (int j = 0; j < 16; ++j)
        #pragma unroll
        for (int c = 0; c < 4; ++c) o_acc[j][c] = 0.f;
    float zlo = 0.f, zhi = 0.f;

    const int bg = (lane >> 3) & 1, bc = (lane >> 4), br = lane & 7;

    __syncthreads();   // Q fragments in regs before B1K is reused
    issue_tile(sb, 0, 0, tid);
    CP_COMMIT();

    for (int t = 0; t < NTILES; ++t) {
        int buf = t & 1;
        __syncthreads();   // readers of buf^1 (tile t-1) done before overwrite
        if (t + 1 < NTILES) issue_tile(sb, buf ^ 1, t + 1, tid);
        CP_COMMIT();
        CP_WAIT1();
        __syncthreads();   // tile t landed + visible

        uint32_t kb = sb + (buf ? B1K : B0K);
        uint32_t vb = sb + (buf ? B1V : B0V);

        #pragma unroll
        for (int s = 0; s < 4; ++s) {
            // ---- S: 16 keys vs warp's 16 query rows (normalized K) ----
            float a0[4] = {0.f, 0.f, 0.f, 0.f}, a1[4] = {0.f, 0.f, 0.f, 0.f};
            #pragma unroll
            for (int k = 0; k < 8; ++k) {
                uint32_t r0, r1, r2, r3;
                ldsm4(r0, r1, r2, r3,
                      kb + (uint32_t)((s * 16 + bg * 8 + br) * SROWK + (k * 16 + bc * 8) * 2));
                mma16816(a0, qa[k], r0, r2);
                mma16816(a1, qa[k], r1, r3);
            }
            // ---- exp(s)-1, Z partials, pack PV A-fragment ----
            float p00 = __expf(a0[0]) - 1.f, p01 = __expf(a0[1]) - 1.f;
            float p02 = __expf(a0[2]) - 1.f, p03 = __expf(a0[3]) - 1.f;
            float p10 = __expf(a1[0]) - 1.f, p11 = __expf(a1[1]) - 1.f;
            float p12 = __expf(a1[2]) - 1.f, p13 = __expf(a1[3]) - 1.f;
            zlo += (p00 + p01) + (p10 + p11);
            zhi += (p02 + p03) + (p12 + p13);
            uint32_t pa[4];
            pa[0] = packh(p01, p00);
            pa[1] = packh(p03, p02);
            pa[2] = packh(p11, p10);
            pa[3] = packh(p13, p12);
            // ---- O += P @ V via V^T tile [d][key], non-trans ldsm ----
            #pragma unroll
            for (int j = 0; j < 8; ++j) {
                uint32_t r0, r1, r2, r3;
                ldsm4(r0, r1, r2, r3,
                      vb + (uint32_t)((j * 16 + bg * 8 + br) * SROWV + (s * 16 + bc * 8) * 2));
                mma16816(o_acc[2 * j],     pa, r0, r2);
                mma16816(o_acc[2 * j + 1], pa, r1, r3);
            }
        }
    }

    // ---- epilogue: Z warp-reduce, add colsum, normalize, write ----
    zlo += __shfl_xor_sync(0xffffffffu, zlo, 1);
    zlo += __shfl_xor_sync(0xffffffffu, zlo, 2);
    zhi += __shfl_xor_sync(0xffffffffu, zhi, 1);
    zhi += __shfl_xor_sync(0xffffffffu, zhi, 2);
    float invZlo = 1.0f / ((float)NKEY + zlo);
    float invZhi = 1.0f / ((float)NKEY + zhi);

    const float* cs = (const float*)(sm + CSOF);
    size_t row0 = (size_t)blockIdx.x * BM + wid * 16 + (lane >> 2);
    int col0 = (lane & 3) * 2;
    #pragma unroll
    for (int j = 0; j < 16; ++j) {
        int c = j * 8 + col0;
        float2 v0 = make_float2((cs[c] + o_acc[j][0]) * invZlo,
                                (cs[c + 1] + o_acc[j][1]) * invZlo);
        float2 v1 = make_float2((cs[c] + o_acc[j][2]) * invZhi,
                                (cs[c + 1] + o_acc[j][3]) * invZhi);
        *(float2*)&out[row0 * DIM + c] = v0;
        *(float2*)&out[(row0 + 8) * DIM + c] = v1;
    }
}

// ---------------- launch ----------------
extern "C" void kernel_launch(void* const* d_in, const int* in_sizes, int n_in,
                              void* d_out, int out_size) {
    const float* queries = (const float*)d_in[0];
    const float* keys    = (const float*)d_in[1];
    float* out = (float*)d_out;
    int N = in_sizes[0] / DIM;

    prep_q<<<N / 8, 256>>>(queries);
    prep_k<<<NKEY / 8, 256>>>(keys);
    prep_colsum<<<DIM, 256>>>(keys);

    cudaFuncSetAttribute(mb_main, cudaFuncAttributeMaxDynamicSharedMemorySize, SMTOT);
    mb_main<<<N / BM, NTHREADS, SMTOT>>>(out);
}

// round 9
// speedup vs baseline: 14.1951x; 1.0274x over previous
#include <cuda_runtime.h>
#include <cuda_fp16.h>
#include <cstdint>

// out = softmax(normalize(Q)@normalize(K)^T) @ K,  N=65536, K=4096, D=128, fp32
// fp16 mma.sync dataflow (proven R7, rel_err 9.5e-5):
//   S  = Qn @ Kn^T  (non-trans ldsm4 on [key][d] tile)
//   O += (exp(S)-1) @ V  (non-trans ldsm4 on V^T [d][key] tile)
//   out = (colsum(V) + O) / Z
// R8: 4-way S accumulator chains + 3-stage cp.async pipeline (1 barrier/tile)
//     + batched ldsm fragment preloads.

#define NQ 65536
#define NKEY 4096
#define DIM 128
#define BM 64
#define BK 64
#define NTILES (NKEY / BK)
#define NTHREADS 128
#define SROWK 272         // K tile row stride bytes (128 fp16 + 16B pad)
#define SROWV 144         // V^T tile row stride bytes (64 fp16 + 16B pad)

__device__ __align__(16) __half g_Qh[(size_t)NQ * DIM];    // normalized Q, fp16
__device__ __align__(16) __half g_Kh[(size_t)NKEY * DIM];  // NORMALIZED keys, fp16
__device__ __align__(16) __half g_Vt[(size_t)DIM * NKEY];  // raw keys^T [d][key], fp16
__device__ __align__(16) float  g_colsum[DIM];             // fp32 colsums of raw keys

// ---------------- helpers ----------------
__device__ __forceinline__ uint32_t smem_u32(const void* p) {
    uint32_t a;
    asm("{ .reg .u64 t; cvta.to.shared.u64 t, %1; cvt.u32.u64 %0, t; }" : "=r"(a) : "l"(p));
    return a;
}
__device__ __forceinline__ void ldsm4(uint32_t* r, uint32_t addr) {
    asm volatile("ldmatrix.sync.aligned.m8n8.x4.shared.b16 {%0,%1,%2,%3}, [%4];"
                 : "=r"(r[0]), "=r"(r[1]), "=r"(r[2]), "=r"(r[3]) : "r"(addr));
}
__device__ __forceinline__ void mma16816(float* d, const uint32_t* a, uint32_t b0, uint32_t b1) {
    asm volatile("mma.sync.aligned.m16n8k16.row.col.f32.f16.f16.f32 "
                 "{%0,%1,%2,%3}, {%4,%5,%6,%7}, {%8,%9}, {%0,%1,%2,%3};"
                 : "+f"(d[0]), "+f"(d[1]), "+f"(d[2]), "+f"(d[3])
                 : "r"(a[0]), "r"(a[1]), "r"(a[2]), "r"(a[3]), "r"(b0), "r"(b1));
}
__device__ __forceinline__ uint32_t packh(float hi, float lo) {
    uint32_t r; asm("cvt.rn.f16x2.f32 %0, %1, %2;" : "=r"(r) : "f"(hi), "f"(lo)); return r;
}
__device__ __forceinline__ void cp16(uint32_t saddr, const void* g) {
    asm volatile("cp.async.cg.shared.global [%0], [%1], 16;" :: "r"(saddr), "l"(g));
}
#define CP_COMMIT() asm volatile("cp.async.commit_group;" ::: "memory")
#define CP_WAIT1()  asm volatile("cp.async.wait_group 1;" ::: "memory")

// ---------------- prep kernels ----------------
__global__ void prep_q(const float* __restrict__ q) {
    int row = blockIdx.x * 8 + (threadIdx.x >> 5);
    int lane = threadIdx.x & 31;
    float4 v = ((const float4*)q)[(size_t)row * 32 + lane];
    float ss = v.x * v.x + v.y * v.y + v.z * v.z + v.w * v.w;
    #pragma unroll
    for (int o = 16; o > 0; o >>= 1) ss += __shfl_xor_sync(0xffffffffu, ss, o);
    float sc = 1.0f / fmaxf(sqrtf(ss), 1e-12f);
    __half2* dst = (__half2*)(g_Qh + (size_t)row * DIM + lane * 4);
    dst[0] = __float22half2_rn(make_float2(v.x * sc, v.y * sc));
    dst[1] = __float22half2_rn(make_float2(v.z * sc, v.w * sc));
}

__global__ void prep_k(const float* __restrict__ keys) {
    int row = blockIdx.x * 8 + (threadIdx.x >> 5);
    int lane = threadIdx.x & 31;
    float4 v = ((const float4*)keys)[(size_t)row * 32 + lane];
    float ss = v.x * v.x + v.y * v.y + v.z * v.z + v.w * v.w;
    #pragma unroll
    for (int o = 16; o > 0; o >>= 1) ss += __shfl_xor_sync(0xffffffffu, ss, o);
    float sc = 1.0f / fmaxf(sqrtf(ss), 1e-12f);
    __half2* dst = (__half2*)(g_Kh + (size_t)row * DIM + lane * 4);
    dst[0] = __float22half2_rn(make_float2(v.x * sc, v.y * sc));
    dst[1] = __float22half2_rn(make_float2(v.z * sc, v.w * sc));
    float xs[4] = {v.x, v.y, v.z, v.w};
    #pragma unroll
    for (int j = 0; j < 4; ++j)
        g_Vt[(size_t)(lane * 4 + j) * NKEY + row] = __float2half(xs[j]);
}

__global__ void prep_colsum(const float* __restrict__ keys) {
    __shared__ float red[256];
    int d = blockIdx.x;
    float s = 0.f;
    for (int k = threadIdx.x; k < NKEY; k += 256) s += keys[(size_t)k * DIM + d];
    red[threadIdx.x] = s;
    __syncthreads();
    for (int o = 128; o > 0; o >>= 1) {
        if ((int)threadIdx.x < o) red[threadIdx.x] += red[threadIdx.x + o];
        __syncthreads();
    }
    if (threadIdx.x == 0) g_colsum[d] = red[0];
}

// ---------------- main kernel ----------------
// smem: 3-stage pipeline { K tile 64x272B ; V^T tile 128x144B } + colsum
#define STG   35840      // bytes per stage (17408 K + 18432 V)
#define VOFF  17408
enum { CSOF = 3 * STG, SMTOT = 3 * STG + 512 };

__device__ __forceinline__ void issue_tile(uint32_t sb, int stg, int t, int tid) {
    uint32_t kb = sb + stg * STG;
    uint32_t vb = kb + VOFF;
    const __half* ks = g_Kh + (size_t)t * BK * DIM;
    const __half* vs = g_Vt + (size_t)t * BK;
    #pragma unroll
    for (int c = 0; c < 8; ++c) {
        int chunk = c * NTHREADS + tid;      // 1024 chunks = 64 rows x 16
        int r = chunk >> 4, o = chunk & 15;
        cp16(kb + r * SROWK + o * 16, ks + (size_t)r * DIM + o * 8);
    }
    #pragma unroll
    for (int c = 0; c < 8; ++c) {
        int chunk = c * NTHREADS + tid;      // 1024 chunks = 128 rows x 8
        int r = chunk >> 3, o = chunk & 7;
        cp16(vb + r * SROWV + o * 16, vs + (size_t)r * NKEY + o * 8);
    }
}

__global__ __launch_bounds__(NTHREADS, 2)
void mb_main(float* __restrict__ out) {
    extern __shared__ char sm[];
    const uint32_t sb = smem_u32(sm);
    const int tid = threadIdx.x, wid = tid >> 5, lane = tid & 31;

    if (tid < DIM) ((float*)(sm + CSOF))[tid] = g_colsum[tid];

    // Stage this CTA's 64-row Q tile into stage-2 K region (full 256B rows).
    {
        const __half* qs = g_Qh + (size_t)blockIdx.x * BM * DIM;
        #pragma unroll
        for (int c = 0; c < 8; ++c) {
            int chunk = c * NTHREADS + tid;  // 1024 chunks = 64 rows x 16
            int r = chunk >> 4, o = chunk & 15;
            *(uint4*)(sm + 2 * STG + r * SROWK + o * 16) =
                *(const uint4*)(qs + (size_t)r * DIM + o * 8);
        }
    }
    // Start the pipeline while Q settles: tiles 0,1 into stages 0,1.
    issue_tile(sb, 0, 0, tid); CP_COMMIT();
    issue_tile(sb, 1, 1, tid); CP_COMMIT();
    __syncthreads();

    uint32_t qa[8][4];
    {
        int row = wid * 16 + (lane & 15);
        int colh = (lane >> 4) * 8;
        #pragma unroll
        for (int k = 0; k < 8; ++k)
            ldsm4(qa[k], sb + 2 * STG + row * SROWK + (k * 16 + colh) * 2);
    }

    float o_acc[16][4];
    #pragma unroll
    for (int j = 0; j < 16; ++j)
        #pragma unroll
        for (int c = 0; c < 4; ++c) o_acc[j][c] = 0.f;
    float zlo = 0.f, zhi = 0.f;

    const int bg = (lane >> 3) & 1, bc = (lane >> 4), br = lane & 7;
    const int krow = bg * 8 + br;

    int stg = 0;       // stage holding tile t
    for (int t = 0; t < NTILES; ++t) {
        CP_WAIT1();        // tile t landed (t+1 may still be in flight)
        __syncthreads();   // visible to all warps; tile t-1 compute done CTA-wide

        // Prefetch tile t+2 into the stage freed by tile t-1 (overlaps compute).
        int wstg = stg - 1; if (wstg < 0) wstg = 2;
        if (t + 2 < NTILES) issue_tile(sb, wstg, t + 2, tid);
        CP_COMMIT();

        uint32_t kb = sb + stg * STG;
        uint32_t vb = kb + VOFF;

        #pragma unroll
        for (int s = 0; s < 4; ++s) {
            // ---- batched K-fragment loads, then S MMAs on 4 chains ----
            uint32_t kf[8][4];
            #pragma unroll
            for (int k = 0; k < 8; ++k)
                ldsm4(kf[k], kb + (uint32_t)((s * 16 + krow) * SROWK + (k * 16 + bc * 8) * 2));
            float a0x[4] = {0,0,0,0}, a0y[4] = {0,0,0,0};
            float a1x[4] = {0,0,0,0}, a1y[4] = {0,0,0,0};
            #pragma unroll
            for (int k = 0; k < 8; k += 2) {
                mma16816(a0x, qa[k],     kf[k][0],     kf[k][2]);
                mma16816(a1x, qa[k],     kf[k][1],     kf[k][3]);
                mma16816(a0y, qa[k + 1], kf[k + 1][0], kf[k + 1][2]);
                mma16816(a1y, qa[k + 1], kf[k + 1][1], kf[k + 1][3]);
            }
            // ---- batched V-fragment loads (overlap with exp) ----
            uint32_t vf[8][4];
            #pragma unroll
            for (int j = 0; j < 8; ++j)
                ldsm4(vf[j], vb + (uint32_t)((j * 16 + krow) * SROWV + (s * 16 + bc * 8) * 2));
            // ---- exp(s)-1, Z partials, pack PV A-fragment ----
            float p00 = __expf(a0x[0] + a0y[0]) - 1.f, p01 = __expf(a0x[1] + a0y[1]) - 1.f;
            float p02 = __expf(a0x[2] + a0y[2]) - 1.f, p03 = __expf(a0x[3] + a0y[3]) - 1.f;
            float p10 = __expf(a1x[0] + a1y[0]) - 1.f, p11 = __expf(a1x[1] + a1y[1]) - 1.f;
            float p12 = __expf(a1x[2] + a1y[2]) - 1.f, p13 = __expf(a1x[3] + a1y[3]) - 1.f;
            zlo += (p00 + p01) + (p10 + p11);
            zhi += (p02 + p03) + (p12 + p13);
            uint32_t pa[4];
            pa[0] = packh(p01, p00);
            pa[1] = packh(p03, p02);
            pa[2] = packh(p11, p10);
            pa[3] = packh(p13, p12);
            // ---- O += P @ V (16 independent accumulator chains) ----
            #pragma unroll
            for (int j = 0; j < 8; ++j) {
                mma16816(o_acc[2 * j],     pa, vf[j][0], vf[j][2]);
                mma16816(o_acc[2 * j + 1], pa, vf[j][1], vf[j][3]);
            }
        }
        if (++stg == 3) stg = 0;
    }

    // ---- epilogue: Z warp-reduce, add colsum, normalize, write ----
    zlo += __shfl_xor_sync(0xffffffffu, zlo, 1);
    zlo += __shfl_xor_sync(0xffffffffu, zlo, 2);
    zhi += __shfl_xor_sync(0xffffffffu, zhi, 1);
    zhi += __shfl_xor_sync(0xffffffffu, zhi, 2);
    float invZlo = 1.0f / ((float)NKEY + zlo);
    float invZhi = 1.0f / ((float)NKEY + zhi);

    const float* cs = (const float*)(sm + CSOF);
    size_t row0 = (size_t)blockIdx.x * BM + wid * 16 + (lane >> 2);
    int col0 = (lane & 3) * 2;
    #pragma unroll
    for (int j = 0; j < 16; ++j) {
        int c = j * 8 + col0;
        float2 v0 = make_float2((cs[c] + o_acc[j][0]) * invZlo,
                                (cs[c + 1] + o_acc[j][1]) * invZlo);
        float2 v1 = make_float2((cs[c] + o_acc[j][2]) * invZhi,
                                (cs[c + 1] + o_acc[j][3]) * invZhi);
        *(float2*)&out[row0 * DIM + c] = v0;
        *(float2*)&out[(row0 + 8) * DIM + c] = v1;
    }
}

// ---------------- launch ----------------
extern "C" void kernel_launch(void* const* d_in, const int* in_sizes, int n_in,
                              void* d_out, int out_size) {
    const float* queries = (const float*)d_in[0];
    const float* keys    = (const float*)d_in[1];
    float* out = (float*)d_out;
    int N = in_sizes[0] / DIM;

    prep_q<<<N / 8, 256>>>(queries);
    prep_k<<<NKEY / 8, 256>>>(keys);
    prep_colsum<<<DIM, 256>>>(keys);

    cudaFuncSetAttribute(mb_main, cudaFuncAttributeMaxDynamicSharedMemorySize, SMTOT);
    mb_main<<<N / BM, NTHREADS, SMTOT>>>(out);
}

// round 10
// speedup vs baseline: 14.2471x; 1.0037x over previous
#include <cuda_runtime.h>
#include <cuda_fp16.h>
#include <cstdint>

// out = softmax(normalize(Q)@normalize(K)^T) @ K,  N=65536, K=4096, D=128, fp32
// fp16 mma.sync dataflow (proven, rel_err 9.5e-5):
//   S  = Qn @ Kn^T  (non-trans ldsm4 on [key][d] tile)   [Qn prescaled by log2e]
//   O += (exp2(S)-1) @ V  (non-trans ldsm4 on V^T [d][key] tile)
//   out = (colsum(V) + O) / Z
// R9: software-pipelined s-loop — S(s+1) MMA burst issues before exp(s)+PV(s)
//     so the tensor pipe stays busy through the MUFU phase; exp2 prescale; JIT
//     V-fragment loads to hold regs under 255.

#define NQ 65536
#define NKEY 4096
#define DIM 128
#define BM 64
#define BK 64
#define NTILES (NKEY / BK)
#define NTHREADS 128
#define SROWK 272         // K tile row stride bytes (128 fp16 + 16B pad)
#define SROWV 144         // V^T tile row stride bytes (64 fp16 + 16B pad)

__device__ __align__(16) __half g_Qh[(size_t)NQ * DIM];    // normalized Q * log2e, fp16
__device__ __align__(16) __half g_Kh[(size_t)NKEY * DIM];  // NORMALIZED keys, fp16
__device__ __align__(16) __half g_Vt[(size_t)DIM * NKEY];  // raw keys^T [d][key], fp16
__device__ __align__(16) float  g_colsum[DIM];             // fp32 colsums of raw keys

// ---------------- helpers ----------------
__device__ __forceinline__ uint32_t smem_u32(const void* p) {
    uint32_t a;
    asm("{ .reg .u64 t; cvta.to.shared.u64 t, %1; cvt.u32.u64 %0, t; }" : "=r"(a) : "l"(p));
    return a;
}
__device__ __forceinline__ void ldsm4(uint32_t* r, uint32_t addr) {
    asm volatile("ldmatrix.sync.aligned.m8n8.x4.shared.b16 {%0,%1,%2,%3}, [%4];"
                 : "=r"(r[0]), "=r"(r[1]), "=r"(r[2]), "=r"(r[3]) : "r"(addr));
}
__device__ __forceinline__ void mma16816(float* d, const uint32_t* a, uint32_t b0, uint32_t b1) {
    asm volatile("mma.sync.aligned.m16n8k16.row.col.f32.f16.f16.f32 "
                 "{%0,%1,%2,%3}, {%4,%5,%6,%7}, {%8,%9}, {%0,%1,%2,%3};"
                 : "+f"(d[0]), "+f"(d[1]), "+f"(d[2]), "+f"(d[3])
                 : "r"(a[0]), "r"(a[1]), "r"(a[2]), "r"(a[3]), "r"(b0), "r"(b1));
}
__device__ __forceinline__ uint32_t packh(float hi, float lo) {
    uint32_t r; asm("cvt.rn.f16x2.f32 %0, %1, %2;" : "=r"(r) : "f"(hi), "f"(lo)); return r;
}
__device__ __forceinline__ void cp16(uint32_t saddr, const void* g) {
    asm volatile("cp.async.cg.shared.global [%0], [%1], 16;" :: "r"(saddr), "l"(g));
}
#define CP_COMMIT() asm volatile("cp.async.commit_group;" ::: "memory")
#define CP_WAIT1()  asm volatile("cp.async.wait_group 1;" ::: "memory")

// ---------------- prep kernels ----------------
__global__ void prep_q(const float* __restrict__ q) {
    int row = blockIdx.x * 8 + (threadIdx.x >> 5);
    int lane = threadIdx.x & 31;
    float4 v = ((const float4*)q)[(size_t)row * 32 + lane];
    float ss = v.x * v.x + v.y * v.y + v.z * v.z + v.w * v.w;
    #pragma unroll
    for (int o = 16; o > 0; o >>= 1) ss += __shfl_xor_sync(0xffffffffu, ss, o);
    // fold log2(e) so scores are in the exp2 domain
    float sc = 1.44269504f / fmaxf(sqrtf(ss), 1e-12f);
    __half2* dst = (__half2*)(g_Qh + (size_t)row * DIM + lane * 4);
    dst[0] = __float22half2_rn(make_float2(v.x * sc, v.y * sc));
    dst[1] = __float22half2_rn(make_float2(v.z * sc, v.w * sc));
}

__global__ void prep_k(const float* __restrict__ keys) {
    int row = blockIdx.x * 8 + (threadIdx.x >> 5);
    int lane = threadIdx.x & 31;
    float4 v = ((const float4*)keys)[(size_t)row * 32 + lane];
    float ss = v.x * v.x + v.y * v.y + v.z * v.z + v.w * v.w;
    #pragma unroll
    for (int o = 16; o > 0; o >>= 1) ss += __shfl_xor_sync(0xffffffffu, ss, o);
    float sc = 1.0f / fmaxf(sqrtf(ss), 1e-12f);
    __half2* dst = (__half2*)(g_Kh + (size_t)row * DIM + lane * 4);
    dst[0] = __float22half2_rn(make_float2(v.x * sc, v.y * sc));
    dst[1] = __float22half2_rn(make_float2(v.z * sc, v.w * sc));
    float xs[4] = {v.x, v.y, v.z, v.w};
    #pragma unroll
    for (int j = 0; j < 4; ++j)
        g_Vt[(size_t)(lane * 4 + j) * NKEY + row] = __float2half(xs[j]);
}

__global__ void prep_colsum(const float* __restrict__ keys) {
    __shared__ float red[256];
    int d = blockIdx.x;
    float s = 0.f;
    for (int k = threadIdx.x; k < NKEY; k += 256) s += keys[(size_t)k * DIM + d];
    red[threadIdx.x] = s;
    __syncthreads();
    for (int o = 128; o > 0; o >>= 1) {
        if ((int)threadIdx.x < o) red[threadIdx.x] += red[threadIdx.x + o];
        __syncthreads();
    }
    if (threadIdx.x == 0) g_colsum[d] = red[0];
}

// ---------------- main kernel ----------------
// smem: 3-stage pipeline { K tile 64x272B ; V^T tile 128x144B } + colsum
#define STG   35840      // bytes per stage (17408 K + 18432 V)
#define VOFF  17408
enum { CSOF = 3 * STG, SMTOT = 3 * STG + 512 };

__device__ __forceinline__ void issue_tile(uint32_t sb, int stg, int t, int tid) {
    uint32_t kb = sb + stg * STG;
    uint32_t vb = kb + VOFF;
    const __half* ks = g_Kh + (size_t)t * BK * DIM;
    const __half* vs = g_Vt + (size_t)t * BK;
    #pragma unroll
    for (int c = 0; c < 8; ++c) {
        int chunk = c * NTHREADS + tid;      // 1024 chunks = 64 rows x 16
        int r = chunk >> 4, o = chunk & 15;
        cp16(kb + r * SROWK + o * 16, ks + (size_t)r * DIM + o * 8);
    }
    #pragma unroll
    for (int c = 0; c < 8; ++c) {
        int chunk = c * NTHREADS + tid;      // 1024 chunks = 128 rows x 8
        int r = chunk >> 3, o = chunk & 7;
        cp16(vb + r * SROWV + o * 16, vs + (size_t)r * NKEY + o * 8);
    }
}

__global__ __launch_bounds__(NTHREADS, 2)
void mb_main(float* __restrict__ out) {
    extern __shared__ char sm[];
    const uint32_t sb = smem_u32(sm);
    const int tid = threadIdx.x, wid = tid >> 5, lane = tid & 31;

    if (tid < DIM) ((float*)(sm + CSOF))[tid] = g_colsum[tid];

    // Stage this CTA's 64-row Q tile into stage-2 K region (full 256B rows).
    {
        const __half* qs = g_Qh + (size_t)blockIdx.x * BM * DIM;
        #pragma unroll
        for (int c = 0; c < 8; ++c) {
            int chunk = c * NTHREADS + tid;  // 1024 chunks = 64 rows x 16
            int r = chunk >> 4, o = chunk & 15;
            *(uint4*)(sm + 2 * STG + r * SROWK + o * 16) =
                *(const uint4*)(qs + (size_t)r * DIM + o * 8);
        }
    }
    // Start the pipeline while Q settles: tiles 0,1 into stages 0,1.
    issue_tile(sb, 0, 0, tid); CP_COMMIT();
    issue_tile(sb, 1, 1, tid); CP_COMMIT();
    __syncthreads();

    uint32_t qa[8][4];
    {
        int row = wid * 16 + (lane & 15);
        int colh = (lane >> 4) * 8;
        #pragma unroll
        for (int k = 0; k < 8; ++k)
            ldsm4(qa[k], sb + 2 * STG + row * SROWK + (k * 16 + colh) * 2);
    }

    float o_acc[16][4];
    #pragma unroll
    for (int j = 0; j < 16; ++j)
        #pragma unroll
        for (int c = 0; c < 4; ++c) o_acc[j][c] = 0.f;
    float zlo = 0.f, zhi = 0.f;

    const int bg = (lane >> 3) & 1, bc = (lane >> 4), br = lane & 7;
    const int krow = bg * 8 + br;

    // S-tile compute: 16 MMAs on 4 chains, pairwise-combined into dst[8].
    #define S_COMP(S_, dst_) do {                                                  \
        uint32_t kf[8][4];                                                         \
        _Pragma("unroll")                                                          \
        for (int k = 0; k < 8; ++k)                                                \
            ldsm4(kf[k], kb + (uint32_t)(((S_) * 16 + krow) * SROWK                \
                                         + (k * 16 + bc * 8) * 2));                \
        float c0[4] = {0,0,0,0}, c1[4] = {0,0,0,0};                                \
        float c2[4] = {0,0,0,0}, c3[4] = {0,0,0,0};                                \
        _Pragma("unroll")                                                          \
        for (int k = 0; k < 8; k += 2) {                                           \
            mma16816(c0, qa[k],     kf[k][0],     kf[k][2]);                       \
            mma16816(c1, qa[k],     kf[k][1],     kf[k][3]);                       \
            mma16816(c2, qa[k + 1], kf[k + 1][0], kf[k + 1][2]);                   \
            mma16816(c3, qa[k + 1], kf[k + 1][1], kf[k + 1][3]);                   \
        }                                                                          \
        _Pragma("unroll")                                                          \
        for (int i = 0; i < 4; ++i) { (dst_)[i] = c0[i] + c2[i];                   \
                                      (dst_)[4 + i] = c1[i] + c3[i]; }             \
    } while (0)

    int stg = 0;       // stage holding tile t
    for (int t = 0; t < NTILES; ++t) {
        CP_WAIT1();        // tile t landed (t+1 may still be in flight)
        __syncthreads();   // visible to all warps; tile t-1 compute done CTA-wide

        // Prefetch tile t+2 into the stage freed by tile t-1 (overlaps compute).
        int wstg = stg - 1; if (wstg < 0) wstg = 2;
        if (t + 2 < NTILES) issue_tile(sb, wstg, t + 2, tid);
        CP_COMMIT();

        uint32_t kb = sb + stg * STG;
        uint32_t vb = kb + VOFF;

        // Software-pipelined s-loop: S(s+1) MMA burst covers exp(s) latency.
        float sacc[2][8];
        S_COMP(0, sacc[0]);
        #pragma unroll
        for (int s = 0; s < 4; ++s) {
            if (s < 3) S_COMP(s + 1, sacc[(s + 1) & 1]);
            const float* sp = sacc[s & 1];
            float p00 = exp2f(sp[0]) - 1.f, p01 = exp2f(sp[1]) - 1.f;
            float p02 = exp2f(sp[2]) - 1.f, p03 = exp2f(sp[3]) - 1.f;
            float p10 = exp2f(sp[4]) - 1.f, p11 = exp2f(sp[5]) - 1.f;
            float p12 = exp2f(sp[6]) - 1.f, p13 = exp2f(sp[7]) - 1.f;
            zlo += (p00 + p01) + (p10 + p11);
            zhi += (p02 + p03) + (p12 + p13);
            uint32_t pa[4];
            pa[0] = packh(p01, p00);
            pa[1] = packh(p03, p02);
            pa[2] = packh(p11, p10);
            pa[3] = packh(p13, p12);
            // O += P @ V (16 independent chains, V fragments JIT)
            #pragma unroll
            for (int j = 0; j < 8; ++j) {
                uint32_t vf[4];
                ldsm4(vf, vb + (uint32_t)((j * 16 + krow) * SROWV + (s * 16 + bc * 8) * 2));
                mma16816(o_acc[2 * j],     pa, vf[0], vf[2]);
                mma16816(o_acc[2 * j + 1], pa, vf[1], vf[3]);
            }
        }
        if (++stg == 3) stg = 0;
    }

    // ---- epilogue: Z warp-reduce, add colsum, normalize, write ----
    zlo += __shfl_xor_sync(0xffffffffu, zlo, 1);
    zlo += __shfl_xor_sync(0xffffffffu, zlo, 2);
    zhi += __shfl_xor_sync(0xffffffffu, zhi, 1);
    zhi += __shfl_xor_sync(0xffffffffu, zhi, 2);
    float invZlo = 1.0f / ((float)NKEY + zlo);
    float invZhi = 1.0f / ((float)NKEY + zhi);

    const float* cs = (const float*)(sm + CSOF);
    size_t row0 = (size_t)blockIdx.x * BM + wid * 16 + (lane >> 2);
    int col0 = (lane & 3) * 2;
    #pragma unroll
    for (int j = 0; j < 16; ++j) {
        int c = j * 8 + col0;
        float2 v0 = make_float2((cs[c] + o_acc[j][0]) * invZlo,
                                (cs[c + 1] + o_acc[j][1]) * invZlo);
        float2 v1 = make_float2((cs[c] + o_acc[j][2]) * invZhi,
                                (cs[c + 1] + o_acc[j][3]) * invZhi);
        *(float2*)&out[row0 * DIM + c] = v0;
        *(float2*)&out[(row0 + 8) * DIM + c] = v1;
    }
}

// ---------------- launch ----------------
extern "C" void kernel_launch(void* const* d_in, const int* in_sizes, int n_in,
                              void* d_out, int out_size) {
    const float* queries = (const float*)d_in[0];
    const float* keys    = (const float*)d_in[1];
    float* out = (float*)d_out;
    int N = in_sizes[0] / DIM;

    prep_q<<<N / 8, 256>>>(queries);
    prep_k<<<NKEY / 8, 256>>>(keys);
    prep_colsum<<<DIM, 256>>>(keys);

    cudaFuncSetAttribute(mb_main, cudaFuncAttributeMaxDynamicSharedMemorySize, SMTOT);
    mb_main<<<N / BM, NTHREADS, SMTOT>>>(out);
}